// round 5
// baseline (speedup 1.0000x reference)
#include <cuda_runtime.h>

// Analytic reduction (see prior rounds): per contiguous 8-float group,
//   c_i = cos(x_i + theta_i)
//   out[j] = prod_{i=0..j} c_i   (j=1..7),   out[0] = prod_{i=1..7} c_i
//
// Launch-overhead bound (all pipes <6%): one group per thread, block=512,
// grid=128 (one flat wave over 128 SMs), no shuffle, streaming stores.
// |phi| <~ 7 so __cosf (MUFU fast path) abs err ~1e-6, far under 1e-3.

__global__ __launch_bounds__(512)
void quantum_heads_kernel(const float* __restrict__ x,
                          const float* __restrict__ theta,
                          float* __restrict__ out,
                          int ngroups)
{
    int g = blockIdx.x * blockDim.x + threadIdx.x;
    if (g >= ngroups) return;

    const float4* tp = reinterpret_cast<const float4*>(theta);
    float4 t0 = __ldg(tp + 0);
    float4 t1 = __ldg(tp + 1);

    const float4* xp = reinterpret_cast<const float4*>(x) + (size_t)g * 2;
    float4 a = __ldg(xp + 0);
    float4 b = __ldg(xp + 1);

    float c0 = __cosf(a.x + t0.x);
    float c1 = __cosf(a.y + t0.y);
    float c2 = __cosf(a.z + t0.z);
    float c3 = __cosf(a.w + t0.w);
    float c4 = __cosf(b.x + t1.x);
    float c5 = __cosf(b.y + t1.y);
    float c6 = __cosf(b.z + t1.z);
    float c7 = __cosf(b.w + t1.w);

    float p1 = c0 * c1;
    float p2 = p1 * c2;
    float p3 = p2 * c3;
    float p4 = p3 * c4;
    float p5 = p4 * c5;
    float p6 = p5 * c6;
    float p7 = p6 * c7;
    // out[0] = c1*...*c7 (suffix; avoid dividing by possibly-zero c0)
    float s = ((c1 * c2) * (c3 * c4)) * ((c5 * c6) * c7);

    float4* op = reinterpret_cast<float4*>(out) + (size_t)g * 2;
    __stcs(op + 0, make_float4(s,  p1, p2, p3));
    __stcs(op + 1, make_float4(p4, p5, p6, p7));
}

extern "C" void kernel_launch(void* const* d_in, const int* in_sizes, int n_in,
                              void* d_out, int out_size)
{
    const float* x     = (const float*)d_in[0];
    const float* theta = (const float*)d_in[1];
    float* out         = (float*)d_out;

    int ngroups = in_sizes[0] / 8;   // one 8-float group (one head) per thread
    int threads = 512;
    int blocks  = (ngroups + threads - 1) / threads;   // 128 for bench shape
    quantum_heads_kernel<<<blocks, threads>>>(x, theta, out, ngroups);
}